// round 8
// baseline (speedup 1.0000x reference)
#include <cuda_runtime.h>
#include <cuda_bf16.h>
#include <cstdint>

// Problem constants (shapes fixed by the dataset)
#define NUM_NODES   10000
#define FEAT        128
#define CAP         256          // per-node edge-list capacity (deg ~ Poisson(64))

// Scratch (no cudaMalloc allowed) — device globals. No float atomics anywhere.
__device__ int   g_cnt[NUM_NODES];
__device__ int   g_elist[NUM_NODES * CAP];
__device__ __align__(16) float g_h[NUM_NODES * FEAT];

// ---------------------------------------------------------------------------
// Kernel 0: zero the per-node counters (must run every launch: graph replay)
// ---------------------------------------------------------------------------
__global__ void zero_kernel() {
    int i = blockIdx.x * blockDim.x + threadIdx.x;
    if (i < NUM_NODES) g_cnt[i] = 0;
}

// ---------------------------------------------------------------------------
// Kernel 1: build adjacency lists. One thread per edge; scalar int atomics only.
// NOTE: edge_index is int32 on device (JAX default config downcasts int64).
// ---------------------------------------------------------------------------
__global__ void fill_kernel(const int* __restrict__ ei, int nedges, int nnodes) {
    int e = blockIdx.x * blockDim.x + threadIdx.x;
    if (e >= nedges) return;
    int src = ei[e];
    int dst = ei[nedges + e];
    // Bounds guard: if the dtype assumption is ever wrong, degrade to a
    // wrong answer (debuggable) instead of an illegal access (opaque).
    if ((unsigned)src >= (unsigned)nnodes || (unsigned)dst >= (unsigned)nnodes)
        return;
    int pos = atomicAdd(&g_cnt[dst], 1);
    if (pos < CAP) g_elist[dst * CAP + pos] = src;
}

// ---------------------------------------------------------------------------
// Kernel 2: gather-aggregate. One warp per node; lane = one float4 chunk.
// h[n] = (sum_{src in adj(n)} x[src]) / max(deg,1) + x[n]
// All x reads are L2-resident; edge-list reads are warp-uniform (broadcast).
// ---------------------------------------------------------------------------
__global__ void gather_kernel(const float* __restrict__ x, int nnodes) {
    int idx  = blockIdx.x * blockDim.x + threadIdx.x;
    int node = idx >> 5;
    int lane = idx & 31;
    if (node >= nnodes) return;

    int deg = g_cnt[node];
    int m   = deg < CAP ? deg : CAP;
    const int* __restrict__ lst = g_elist + node * CAP;

    float4 acc = make_float4(0.f, 0.f, 0.f, 0.f);
#pragma unroll 4
    for (int i = 0; i < m; i++) {
        int src = __ldg(&lst[i]);   // warp-uniform -> broadcast
        float4 v = __ldg(((const float4*)(x + (long)src * FEAT)) + lane);
        acc.x += v.x; acc.y += v.y; acc.z += v.z; acc.w += v.w;
    }

    float inv = 1.0f / fmaxf((float)deg, 1.0f);
    float4 xr = __ldg(((const float4*)(x + (long)node * FEAT)) + lane);
    float4 h;
    h.x = acc.x * inv + xr.x;
    h.y = acc.y * inv + xr.y;
    h.z = acc.z * inv + xr.z;
    h.w = acc.w * inv + xr.w;
    ((float4*)(g_h + (long)node * FEAT))[lane] = h;
}

// ---------------------------------------------------------------------------
// Kernel 3: out = relu(h @ W^T + b)
// Block: 256 threads, 80-row tile -> 125 blocks (single wave on 148 SMs).
//   Ws: [128 cols][132 padded] floats, hs: [80][128].
//   Thread t: rg = t>>5 (constant per warp -> hs loads broadcast),
//             cg = t&31, columns {cg, cg+32, cg+64, cg+96}
//             (interleaved -> conflict-free LDS.128 phases on Ws).
//   Register tile 10 rows x 4 cols.
// ---------------------------------------------------------------------------
#define ROWS_PER_BLOCK 80
#define W_STRIDE 132
#define GEMM_SMEM (FEAT * W_STRIDE * 4 + ROWS_PER_BLOCK * FEAT * 4)

__global__ __launch_bounds__(256, 1)
void gemm_kernel(const float* __restrict__ W,
                 const float* __restrict__ b,
                 float* __restrict__ out,
                 int nnodes) {
    extern __shared__ float smem[];
    float* Ws = smem;                      // [o][d] padded stride 132
    float* hs = smem + FEAT * W_STRIDE;    // [80][128]

    int row0 = blockIdx.x * ROWS_PER_BLOCK;
    int t = threadIdx.x;

    // Load W into shared: W[o][d] -> Ws[o*132 + d] (coalesced global reads)
    for (int i = t; i < FEAT * FEAT; i += 256) {
        int o = i >> 7;
        int d = i & 127;
        Ws[o * W_STRIDE + d] = W[i];
    }

    // Load h tile (float4, coalesced)
    for (int i = t; i < ROWS_PER_BLOCK * FEAT / 4; i += 256) {
        int n = i / (FEAT / 4);
        int d4 = i % (FEAT / 4);
        int node = row0 + n;
        float4 v = make_float4(0.f, 0.f, 0.f, 0.f);
        if (node < nnodes)
            v = ((const float4*)(g_h + (long)node * FEAT))[d4];
        ((float4*)hs)[i] = v;
    }
    __syncthreads();

    int cg = t & 31;        // column lane: cols cg + 32*j
    int rg = t >> 5;        // warp id = row group: rows rg*10 .. rg*10+9

    float acc[10][4];
#pragma unroll
    for (int r = 0; r < 10; r++)
#pragma unroll
        for (int j = 0; j < 4; j++) acc[r][j] = 0.0f;

#pragma unroll 4
    for (int d4 = 0; d4 < FEAT / 4; d4++) {
        float4 w[4];
#pragma unroll
        for (int j = 0; j < 4; j++)
            w[j] = *(const float4*)&Ws[(cg + 32 * j) * W_STRIDE + d4 * 4];
#pragma unroll
        for (int r = 0; r < 10; r++) {
            float4 h = *(const float4*)&hs[(rg * 10 + r) * FEAT + d4 * 4];
#pragma unroll
            for (int j = 0; j < 4; j++) {
                acc[r][j] = fmaf(h.x, w[j].x,
                            fmaf(h.y, w[j].y,
                            fmaf(h.z, w[j].z,
                            fmaf(h.w, w[j].w, acc[r][j]))));
            }
        }
    }

    float bias[4];
#pragma unroll
    for (int j = 0; j < 4; j++) bias[j] = b[cg + 32 * j];

#pragma unroll
    for (int r = 0; r < 10; r++) {
        int node = row0 + rg * 10 + r;
        if (node < nnodes) {
#pragma unroll
            for (int j = 0; j < 4; j++)
                out[(long)node * FEAT + cg + 32 * j] =
                    fmaxf(acc[r][j] + bias[j], 0.0f);
        }
    }
}

// ---------------------------------------------------------------------------
// Launch: zero -> fill -> gather -> gemm (stream-ordered on capture stream)
// ---------------------------------------------------------------------------
extern "C" void kernel_launch(void* const* d_in, const int* in_sizes, int n_in,
                              void* d_out, int out_size) {
    const float* x  = (const float*)d_in[0];
    const int*   ei = (const int*)d_in[1];   // int32! (JAX default x64-disabled)
    const float* W  = (const float*)d_in[2];
    const float* b  = (const float*)d_in[3];
    float*       out = (float*)d_out;

    int nnodes = in_sizes[0] / FEAT;
    int nedges = in_sizes[1] / 2;

    cudaFuncSetAttribute(gemm_kernel,
                         cudaFuncAttributeMaxDynamicSharedMemorySize,
                         GEMM_SMEM);

    zero_kernel<<<(NUM_NODES + 255) / 256, 256>>>();

    fill_kernel<<<(nedges + 255) / 256, 256>>>(ei, nedges, nnodes);

    {
        long threads = (long)nnodes * 32;
        int blocks = (int)((threads + 255) / 256);
        gather_kernel<<<blocks, 256>>>(x, nnodes);
    }
    {
        int blocks = (nnodes + ROWS_PER_BLOCK - 1) / ROWS_PER_BLOCK;
        gemm_kernel<<<blocks, 256, GEMM_SMEM>>>(W, b, out, nnodes);
    }
}